// round 1
// baseline (speedup 1.0000x reference)
#include <cuda_runtime.h>
#include <math.h>

// Problem constants (fixed by the dataset)
#define DD    128          // embedding dim
#define BT    64           // session tile
#define PT    64           // pool tile per chunk
#define PS    9            // P splits (32 btiles * 9 = 288 CTAs ~ 148*2 slots)
#define MAXB  2048
#define MAXP  100000
#define EPSV  1e-6f
#define ROWP  132          // smem row pitch (floats) for 128-wide rows
#define SCP   68           // score tile row pitch
#define NEGF  (-3.0e38f)

// ---------------- device scratch (no allocations allowed) ----------------
__device__ float g_poolInv[MAXP];
__device__ float g_sessInv[MAXB];
__device__ float g_pZ[MAXB * PS];
__device__ float g_pV[MAXB * PS * 3];
__device__ int   g_pI[MAXB * PS * 3];

// ---------------- helpers ----------------
__device__ __forceinline__ void ins3(float v, int idx,
    float& v0, float& v1, float& v2, int& i0, int& i1, int& i2)
{
    // descending by value, ties broken by smaller index (lax.top_k semantics)
    bool b2 = (v > v2) || (v == v2 && idx < i2);
    if (!b2) return;
    bool b1 = (v > v1) || (v == v1 && idx < i1);
    if (b1) {
        v2 = v1; i2 = i1;
        bool b0 = (v > v0) || (v == v0 && idx < i0);
        if (b0) { v1 = v0; i1 = i0; v0 = v; i0 = idx; }
        else    { v1 = v;  i1 = idx; }
    } else { v2 = v; i2 = idx; }
}

// ---------------- inverse norms: one warp per row ----------------
__global__ void norm_kernel(const float* __restrict__ x,
                            float* __restrict__ inv, int n)
{
    int w    = (blockIdx.x * blockDim.x + threadIdx.x) >> 5;
    int lane = threadIdx.x & 31;
    if (w >= n) return;
    float4 v = *(const float4*)(x + (size_t)w * DD + lane * 4);
    float s = v.x * v.x + v.y * v.y + v.z * v.z + v.w * v.w;
    #pragma unroll
    for (int d = 16; d; d >>= 1) s += __shfl_xor_sync(0xffffffffu, s, d);
    if (lane == 0) inv[w] = 1.0f / sqrtf(s + DD * EPSV);
}

// ---------------- fused GEMM + online softmax-Z + top-3 ----------------
extern __shared__ float smem[];

__global__ void __launch_bounds__(256, 2)
score_kernel(const float* __restrict__ sess, const float* __restrict__ pool,
             int B, int P, int Pchunk)
{
    float* sS    = smem;                  // BT*ROWP
    float* pS    = sS + BT * ROWP;        // PT*ROWP
    float* scS   = pS + PT * ROWP;        // BT*SCP
    float* sInvS = scS + BT * SCP;        // BT

    const int tid = threadIdx.x;
    const int b0  = blockIdx.x * BT;
    const int p0  = blockIdx.y * Pchunk;
    const int p1  = min(p0 + Pchunk, P);

    // load session tile (coalesced float4, row-major padded)
    #pragma unroll
    for (int t = 0; t < 8; t++) {
        int i4  = tid + t * 256;       // 0..2047
        int row = i4 >> 5, c4 = i4 & 31;
        float4 v = *(const float4*)(sess + (size_t)(b0 + row) * DD + c4 * 4);
        *(float4*)(sS + row * ROWP + c4 * 4) = v;
    }
    if (tid < BT) sInvS[tid] = g_sessInv[b0 + tid];

    const int tx = tid & 15, ty = tid >> 4;   // GEMM roles
    const int r  = tid >> 2, part = tid & 3;  // reduce roles (4 lanes/row)

    float Zrun = 0.f;
    float rv0 = NEGF, rv1 = NEGF, rv2 = NEGF;
    int   ri0 = 0x7fffffff, ri1 = 0x7fffffff, ri2 = 0x7fffffff;

    for (int c = p0; c < p1; c += PT) {
        __syncthreads();   // pS/scS safe to overwrite

        // load pool chunk
        #pragma unroll
        for (int t = 0; t < 8; t++) {
            int i4  = tid + t * 256;
            int row = i4 >> 5, c4 = i4 & 31;
            int gp  = c + row;
            float4 v = (gp < P)
                ? *(const float4*)(pool + (size_t)gp * DD + c4 * 4)
                : make_float4(0.f, 0.f, 0.f, 0.f);
            *(float4*)(pS + row * ROWP + c4 * 4) = v;
        }
        __syncthreads();

        // 64x64x128 fp32 GEMM, 4x4 micro-tile, strided-16 column ownership
        float acc[4][4] = {};
        #pragma unroll 4
        for (int k4 = 0; k4 < 32; k4++) {
            float4 a[4], b[4];
            #pragma unroll
            for (int i = 0; i < 4; i++)
                a[i] = *(float4*)(sS + (ty + 16 * i) * ROWP + k4 * 4);
            #pragma unroll
            for (int j = 0; j < 4; j++)
                b[j] = *(float4*)(pS + (tx + 16 * j) * ROWP + k4 * 4);
            #pragma unroll
            for (int i = 0; i < 4; i++)
                #pragma unroll
                for (int j = 0; j < 4; j++) {
                    acc[i][j] += a[i].x * b[j].x;
                    acc[i][j] += a[i].y * b[j].y;
                    acc[i][j] += a[i].z * b[j].z;
                    acc[i][j] += a[i].w * b[j].w;
                }
        }

        // cosine scores -> smem (mask columns beyond this split)
        #pragma unroll
        for (int j = 0; j < 4; j++) {
            int col = tx + 16 * j;
            int gp  = c + col;
            bool valid = gp < p1;
            float pInv = valid ? g_poolInv[gp] : 0.f;
            #pragma unroll
            for (int i = 0; i < 4; i++) {
                int row = ty + 16 * i;
                float sc = valid ? acc[i][j] * (sInvS[row] * pInv) : NEGF;
                scS[row * SCP + col] = sc;
            }
        }
        __syncthreads();

        // per-row reduce: 4 lanes scan 16 cols each
        float Zl = 0.f;
        float l0 = NEGF, l1 = NEGF, l2 = NEGF;
        int   j0 = 0x7fffffff, j1 = 0x7fffffff, j2 = 0x7fffffff;
        #pragma unroll
        for (int cc = 0; cc < 16; cc++) {
            int col = part * 16 + cc;
            float v = scS[r * SCP + col];
            Zl += __expf(v - 1.0f);          // NEGF -> exp underflows to 0
            ins3(v, c + col, l0, l1, l2, j0, j1, j2);
        }
        // butterfly merge across the 4 lanes of this row (replicated result)
        #pragma unroll
        for (int d = 1; d <= 2; d <<= 1) {
            float o0 = __shfl_xor_sync(0xffffffffu, l0, d);
            float o1 = __shfl_xor_sync(0xffffffffu, l1, d);
            float o2 = __shfl_xor_sync(0xffffffffu, l2, d);
            int   q0 = __shfl_xor_sync(0xffffffffu, j0, d);
            int   q1 = __shfl_xor_sync(0xffffffffu, j1, d);
            int   q2 = __shfl_xor_sync(0xffffffffu, j2, d);
            float zo = __shfl_xor_sync(0xffffffffu, Zl, d);
            ins3(o0, q0, l0, l1, l2, j0, j1, j2);
            ins3(o1, q1, l0, l1, l2, j0, j1, j2);
            ins3(o2, q2, l0, l1, l2, j0, j1, j2);
            Zl += zo;
        }
        Zrun += Zl;
        ins3(l0, j0, rv0, rv1, rv2, ri0, ri1, ri2);
        ins3(l1, j1, rv0, rv1, rv2, ri0, ri1, ri2);
        ins3(l2, j2, rv0, rv1, rv2, ri0, ri1, ri2);
    }

    if (part == 0) {
        int b = b0 + r;
        int o = b * PS + blockIdx.y;
        g_pZ[o] = Zrun;
        g_pV[o * 3 + 0] = rv0; g_pI[o * 3 + 0] = ri0;
        g_pV[o * 3 + 1] = rv1; g_pI[o * 3 + 1] = ri1;
        g_pV[o * 3 + 2] = rv2; g_pI[o * 3 + 2] = ri2;
    }
}

// ---------------- combine: merge splits, softmaxes, gather, outputs ----------------
__global__ void combine_kernel(const float* __restrict__ pool,
                               float* __restrict__ out, int B, int P)
{
    int w    = (blockIdx.x * blockDim.x + threadIdx.x) >> 5;
    int lane = threadIdx.x & 31;
    if (w >= B) return;
    int b = w;

    float w0 = 0.f, w1 = 0.f, w2 = 0.f;
    int   i0 = 0, i1 = 0, i2 = 0;
    if (lane == 0) {
        float Z = 0.f;
        float v0 = NEGF, v1 = NEGF, v2 = NEGF;
        int   k0 = 0x7fffffff, k1 = 0x7fffffff, k2 = 0x7fffffff;
        for (int s = 0; s < PS; s++) {
            int o = b * PS + s;
            Z += g_pZ[o];
            #pragma unroll
            for (int t = 0; t < 3; t++)
                ins3(g_pV[o * 3 + t], g_pI[o * 3 + t], v0, v1, v2, k0, k1, k2);
        }
        float invZ = 1.0f / Z;
        float q0 = __expf(v0 - 1.0f) * invZ;   // first-softmax probs at top-3
        float q1 = __expf(v1 - 1.0f) * invZ;
        float q2 = __expf(v2 - 1.0f) * invZ;
        float m  = fmaxf(q0, fmaxf(q1, q2));
        float e0 = __expf(q0 - m), e1 = __expf(q1 - m), e2 = __expf(q2 - m);
        float inv = 1.0f / (e0 + e1 + e2);
        w0 = e0 * inv; w1 = e1 * inv; w2 = e2 * inv;
        i0 = k0; i1 = k1; i2 = k2;
    }
    w0 = __shfl_sync(0xffffffffu, w0, 0);
    w1 = __shfl_sync(0xffffffffu, w1, 0);
    w2 = __shfl_sync(0xffffffffu, w2, 0);
    i0 = __shfl_sync(0xffffffffu, i0, 0);
    i1 = __shfl_sync(0xffffffffu, i1, 0);
    i2 = __shfl_sync(0xffffffffu, i2, 0);

    float* outN = out;                                   // [B,128]
    float* outC = out + (size_t)B * DD;                  // [B,3]
    float* outT = outC + (size_t)B * 3;                  // [B,3,128]

    if (lane == 0) {
        outC[b * 3 + 0] = w0;
        outC[b * 3 + 1] = w1;
        outC[b * 3 + 2] = w2;
    }

    float4 t0 = *(const float4*)(pool + (size_t)i0 * DD + lane * 4);
    float4 t1 = *(const float4*)(pool + (size_t)i1 * DD + lane * 4);
    float4 t2 = *(const float4*)(pool + (size_t)i2 * DD + lane * 4);

    *(float4*)(outT + ((size_t)b * 3 + 0) * DD + lane * 4) = t0;
    *(float4*)(outT + ((size_t)b * 3 + 1) * DD + lane * 4) = t1;
    *(float4*)(outT + ((size_t)b * 3 + 2) * DD + lane * 4) = t2;

    float4 nb;
    nb.x = w0 * t0.x + w1 * t1.x + w2 * t2.x;
    nb.y = w0 * t0.y + w1 * t1.y + w2 * t2.y;
    nb.z = w0 * t0.z + w1 * t1.z + w2 * t2.z;
    nb.w = w0 * t0.w + w1 * t1.w + w2 * t2.w;
    *(float4*)(outN + (size_t)b * DD + lane * 4) = nb;
}

// ---------------- launch ----------------
extern "C" void kernel_launch(void* const* d_in, const int* in_sizes, int n_in,
                              void* d_out, int out_size)
{
    const float* sess = (const float*)d_in[0];
    const float* pool = (const float*)d_in[1];
    float* out = (float*)d_out;

    int B = in_sizes[0] / DD;   // 2048
    int P = in_sizes[1] / DD;   // 100000
    int Pchunk = (P + PS - 1) / PS;

    // inverse norms
    float* d_poolInv; cudaGetSymbolAddress((void**)&d_poolInv, g_poolInv);
    float* d_sessInv; cudaGetSymbolAddress((void**)&d_sessInv, g_sessInv);
    norm_kernel<<<(P + 7) / 8, 256>>>(pool, d_poolInv, P);
    norm_kernel<<<(B + 7) / 8, 256>>>(sess, d_sessInv, B);

    // fused score pass
    size_t smemBytes = (size_t)(BT * ROWP + PT * ROWP + BT * SCP + BT) * sizeof(float);
    cudaFuncSetAttribute(score_kernel,
                         cudaFuncAttributeMaxDynamicSharedMemorySize,
                         (int)smemBytes);
    dim3 grid1(B / BT, PS);
    score_kernel<<<grid1, 256, smemBytes>>>(sess, pool, B, P, Pchunk);

    // combine
    combine_kernel<<<(B + 7) / 8, 256>>>(pool, out, B, P);
}

// round 2
// speedup vs baseline: 1.1542x; 1.1542x over previous
#include <cuda_runtime.h>
#include <math.h>

// Problem constants (fixed by the dataset)
#define DD    128          // embedding dim
#define BT    64           // session tile
#define PT    64           // pool tile per chunk
#define PS    9            // P splits (32 btiles * 9 = 288 CTAs ~ 148*2 slots)
#define MAXB  2048
#define MAXP  100000
#define EPSV  1e-6f
#define ROWP  132          // smem row pitch (floats) for 128-wide rows
#define SCP   68           // score tile row pitch
#define NEGF  (-3.0e38f)

typedef unsigned long long u64;

// packed dual-fp32 FMA (Blackwell FFMA2) — only reachable via PTX
#define FMA2(d, a, b) \
    asm("fma.rn.f32x2 %0, %1, %2, %0;" : "+l"(d) : "l"(a), "l"(b))

#define UNPACK2(lo, hi, p) \
    asm("mov.b64 {%0, %1}, %2;" : "=f"(lo), "=f"(hi) : "l"(p))

// ---------------- device scratch (no allocations allowed) ----------------
__device__ float g_poolInv[MAXP];
__device__ float g_sessInv[MAXB];
__device__ float g_pZ[MAXB * PS];
__device__ float g_pV[MAXB * PS * 3];
__device__ int   g_pI[MAXB * PS * 3];

// ---------------- helpers ----------------
__device__ __forceinline__ void ins3(float v, int idx,
    float& v0, float& v1, float& v2, int& i0, int& i1, int& i2)
{
    // descending by value, ties broken by smaller index (lax.top_k semantics)
    bool b2 = (v > v2) || (v == v2 && idx < i2);
    if (!b2) return;
    bool b1 = (v > v1) || (v == v1 && idx < i1);
    if (b1) {
        v2 = v1; i2 = i1;
        bool b0 = (v > v0) || (v == v0 && idx < i0);
        if (b0) { v1 = v0; i1 = i0; v0 = v; i0 = idx; }
        else    { v1 = v;  i1 = idx; }
    } else { v2 = v; i2 = idx; }
}

// ---------------- inverse norms: one warp per row ----------------
__global__ void norm_kernel(const float* __restrict__ x,
                            float* __restrict__ inv, int n)
{
    int w    = (blockIdx.x * blockDim.x + threadIdx.x) >> 5;
    int lane = threadIdx.x & 31;
    if (w >= n) return;
    float4 v = *(const float4*)(x + (size_t)w * DD + lane * 4);
    float s = v.x * v.x + v.y * v.y + v.z * v.z + v.w * v.w;
    #pragma unroll
    for (int d = 16; d; d >>= 1) s += __shfl_xor_sync(0xffffffffu, s, d);
    if (lane == 0) inv[w] = 1.0f / sqrtf(s + DD * EPSV);
}

// ---------------- fused GEMM + online softmax-Z + top-3 ----------------
extern __shared__ float smem[];

__global__ void __launch_bounds__(256, 2)
score_kernel(const float* __restrict__ sess, const float* __restrict__ pool,
             int B, int P, int Pchunk)
{
    float* sS    = smem;                  // BT*ROWP
    float* pS    = sS + BT * ROWP;        // PT*ROWP
    float* scS   = pS + PT * ROWP;        // BT*SCP
    float* sInvS = scS + BT * SCP;        // BT

    const int tid = threadIdx.x;
    const int b0  = blockIdx.x * BT;
    const int p0  = blockIdx.y * Pchunk;
    const int p1  = min(p0 + Pchunk, P);

    // load session tile (coalesced float4, row-major padded)
    #pragma unroll
    for (int t = 0; t < 8; t++) {
        int i4  = tid + t * 256;       // 0..2047
        int row = i4 >> 5, c4 = i4 & 31;
        float4 v = *(const float4*)(sess + (size_t)(b0 + row) * DD + c4 * 4);
        *(float4*)(sS + row * ROWP + c4 * 4) = v;
    }
    if (tid < BT) sInvS[tid] = g_sessInv[b0 + tid];

    const int tx = tid & 15, ty = tid >> 4;   // GEMM roles
    const int r  = tid >> 2, part = tid & 3;  // reduce roles (4 lanes/row)

    float Zrun = 0.f;
    float rv0 = NEGF, rv1 = NEGF, rv2 = NEGF;
    int   ri0 = 0x7fffffff, ri1 = 0x7fffffff, ri2 = 0x7fffffff;

    for (int c = p0; c < p1; c += PT) {
        __syncthreads();   // pS/scS safe to overwrite

        // load pool chunk
        #pragma unroll
        for (int t = 0; t < 8; t++) {
            int i4  = tid + t * 256;
            int row = i4 >> 5, c4 = i4 & 31;
            int gp  = c + row;
            float4 v = (gp < P)
                ? *(const float4*)(pool + (size_t)gp * DD + c4 * 4)
                : make_float4(0.f, 0.f, 0.f, 0.f);
            *(float4*)(pS + row * ROWP + c4 * 4) = v;
        }
        __syncthreads();

        // 64x64x128 fp32 GEMM, 4x4 micro-tile, strided-16 column ownership.
        // k-dimension packed in pairs: each FFMA2 does 2 k-steps, accumulator
        // holds (even-k partial, odd-k partial); exact fp32 per lane.
        u64 acc2[4][4] = {};
        #pragma unroll 4
        for (int k4 = 0; k4 < 32; k4++) {
            ulonglong2 a2[4], b2[4];
            #pragma unroll
            for (int i = 0; i < 4; i++)
                a2[i] = *(ulonglong2*)(sS + (ty + 16 * i) * ROWP + k4 * 4);
            #pragma unroll
            for (int j = 0; j < 4; j++)
                b2[j] = *(ulonglong2*)(pS + (tx + 16 * j) * ROWP + k4 * 4);
            #pragma unroll
            for (int i = 0; i < 4; i++)
                #pragma unroll
                for (int j = 0; j < 4; j++) {
                    FMA2(acc2[i][j], a2[i].x, b2[j].x);
                    FMA2(acc2[i][j], a2[i].y, b2[j].y);
                }
        }

        // cosine scores -> smem (mask columns beyond this split)
        #pragma unroll
        for (int j = 0; j < 4; j++) {
            int col = tx + 16 * j;
            int gp  = c + col;
            bool valid = gp < p1;
            float pInv = valid ? g_poolInv[gp] : 0.f;
            #pragma unroll
            for (int i = 0; i < 4; i++) {
                int row = ty + 16 * i;
                float lo, hi;
                UNPACK2(lo, hi, acc2[i][j]);
                float dot = lo + hi;
                float sc = valid ? dot * (sInvS[row] * pInv) : NEGF;
                scS[row * SCP + col] = sc;
            }
        }
        __syncthreads();

        // per-row reduce: 4 lanes scan 16 cols each
        float Zl = 0.f;
        float l0 = NEGF, l1 = NEGF, l2 = NEGF;
        int   j0 = 0x7fffffff, j1 = 0x7fffffff, j2 = 0x7fffffff;
        #pragma unroll
        for (int cc = 0; cc < 16; cc++) {
            int col = part * 16 + cc;
            float v = scS[r * SCP + col];
            Zl += __expf(v - 1.0f);          // NEGF -> exp underflows to 0
            ins3(v, c + col, l0, l1, l2, j0, j1, j2);
        }
        // butterfly merge across the 4 lanes of this row (replicated result)
        #pragma unroll
        for (int d = 1; d <= 2; d <<= 1) {
            float o0 = __shfl_xor_sync(0xffffffffu, l0, d);
            float o1 = __shfl_xor_sync(0xffffffffu, l1, d);
            float o2 = __shfl_xor_sync(0xffffffffu, l2, d);
            int   q0 = __shfl_xor_sync(0xffffffffu, j0, d);
            int   q1 = __shfl_xor_sync(0xffffffffu, j1, d);
            int   q2 = __shfl_xor_sync(0xffffffffu, j2, d);
            float zo = __shfl_xor_sync(0xffffffffu, Zl, d);
            ins3(o0, q0, l0, l1, l2, j0, j1, j2);
            ins3(o1, q1, l0, l1, l2, j0, j1, j2);
            ins3(o2, q2, l0, l1, l2, j0, j1, j2);
            Zl += zo;
        }
        Zrun += Zl;
        ins3(l0, j0, rv0, rv1, rv2, ri0, ri1, ri2);
        ins3(l1, j1, rv0, rv1, rv2, ri0, ri1, ri2);
        ins3(l2, j2, rv0, rv1, rv2, ri0, ri1, ri2);
    }

    if (part == 0) {
        int b = b0 + r;
        int o = b * PS + blockIdx.y;
        g_pZ[o] = Zrun;
        g_pV[o * 3 + 0] = rv0; g_pI[o * 3 + 0] = ri0;
        g_pV[o * 3 + 1] = rv1; g_pI[o * 3 + 1] = ri1;
        g_pV[o * 3 + 2] = rv2; g_pI[o * 3 + 2] = ri2;
    }
}

// ---------------- combine: merge splits, softmaxes, gather, outputs ----------------
__global__ void combine_kernel(const float* __restrict__ pool,
                               float* __restrict__ out, int B, int P)
{
    int w    = (blockIdx.x * blockDim.x + threadIdx.x) >> 5;
    int lane = threadIdx.x & 31;
    if (w >= B) return;
    int b = w;

    float w0 = 0.f, w1 = 0.f, w2 = 0.f;
    int   i0 = 0, i1 = 0, i2 = 0;
    if (lane == 0) {
        float Z = 0.f;
        float v0 = NEGF, v1 = NEGF, v2 = NEGF;
        int   k0 = 0x7fffffff, k1 = 0x7fffffff, k2 = 0x7fffffff;
        for (int s = 0; s < PS; s++) {
            int o = b * PS + s;
            Z += g_pZ[o];
            #pragma unroll
            for (int t = 0; t < 3; t++)
                ins3(g_pV[o * 3 + t], g_pI[o * 3 + t], v0, v1, v2, k0, k1, k2);
        }
        float invZ = 1.0f / Z;
        float q0 = __expf(v0 - 1.0f) * invZ;   // first-softmax probs at top-3
        float q1 = __expf(v1 - 1.0f) * invZ;
        float q2 = __expf(v2 - 1.0f) * invZ;
        float m  = fmaxf(q0, fmaxf(q1, q2));
        float e0 = __expf(q0 - m), e1 = __expf(q1 - m), e2 = __expf(q2 - m);
        float inv = 1.0f / (e0 + e1 + e2);
        w0 = e0 * inv; w1 = e1 * inv; w2 = e2 * inv;
        i0 = k0; i1 = k1; i2 = k2;
    }
    w0 = __shfl_sync(0xffffffffu, w0, 0);
    w1 = __shfl_sync(0xffffffffu, w1, 0);
    w2 = __shfl_sync(0xffffffffu, w2, 0);
    i0 = __shfl_sync(0xffffffffu, i0, 0);
    i1 = __shfl_sync(0xffffffffu, i1, 0);
    i2 = __shfl_sync(0xffffffffu, i2, 0);

    float* outN = out;                                   // [B,128]
    float* outC = out + (size_t)B * DD;                  // [B,3]
    float* outT = outC + (size_t)B * 3;                  // [B,3,128]

    if (lane == 0) {
        outC[b * 3 + 0] = w0;
        outC[b * 3 + 1] = w1;
        outC[b * 3 + 2] = w2;
    }

    float4 t0 = *(const float4*)(pool + (size_t)i0 * DD + lane * 4);
    float4 t1 = *(const float4*)(pool + (size_t)i1 * DD + lane * 4);
    float4 t2 = *(const float4*)(pool + (size_t)i2 * DD + lane * 4);

    *(float4*)(outT + ((size_t)b * 3 + 0) * DD + lane * 4) = t0;
    *(float4*)(outT + ((size_t)b * 3 + 1) * DD + lane * 4) = t1;
    *(float4*)(outT + ((size_t)b * 3 + 2) * DD + lane * 4) = t2;

    float4 nb;
    nb.x = w0 * t0.x + w1 * t1.x + w2 * t2.x;
    nb.y = w0 * t0.y + w1 * t1.y + w2 * t2.y;
    nb.z = w0 * t0.z + w1 * t1.z + w2 * t2.z;
    nb.w = w0 * t0.w + w1 * t1.w + w2 * t2.w;
    *(float4*)(outN + (size_t)b * DD + lane * 4) = nb;
}

// ---------------- launch ----------------
extern "C" void kernel_launch(void* const* d_in, const int* in_sizes, int n_in,
                              void* d_out, int out_size)
{
    const float* sess = (const float*)d_in[0];
    const float* pool = (const float*)d_in[1];
    float* out = (float*)d_out;

    int B = in_sizes[0] / DD;   // 2048
    int P = in_sizes[1] / DD;   // 100000
    int Pchunk = (P + PS - 1) / PS;

    // inverse norms
    float* d_poolInv; cudaGetSymbolAddress((void**)&d_poolInv, g_poolInv);
    float* d_sessInv; cudaGetSymbolAddress((void**)&d_sessInv, g_sessInv);
    norm_kernel<<<(P + 7) / 8, 256>>>(pool, d_poolInv, P);
    norm_kernel<<<(B + 7) / 8, 256>>>(sess, d_sessInv, B);

    // fused score pass
    size_t smemBytes = (size_t)(BT * ROWP + PT * ROWP + BT * SCP + BT) * sizeof(float);
    cudaFuncSetAttribute(score_kernel,
                         cudaFuncAttributeMaxDynamicSharedMemorySize,
                         (int)smemBytes);
    dim3 grid1(B / BT, PS);
    score_kernel<<<grid1, 256, smemBytes>>>(sess, pool, B, P, Pchunk);

    // combine
    combine_kernel<<<(B + 7) / 8, 256>>>(pool, out, B, P);
}